// round 8
// baseline (speedup 1.0000x reference)
#include <cuda_runtime.h>
#include <cuda_bf16.h>

#define NE 100000
#define NN 10000
#define PI_F 3.14159265358979323846f
#define SQRT_2_CUT 0.6030226891555273f

__device__ int g_cnt[NN];      // statically zero-init; gather re-zeroes after reading
__device__ int g_start[NN];
__device__ int g_cursor[NN];
__device__ int g_order[NE];
// Payload per edge: 32 floats (128B): [0:20)=mon_a*sc, [20]=sign word, [21:24)=pad, [24:32)=sin(n*theta)
__device__ __align__(128) float g_pay[NE * 32];

// prep: per-edge payload (coalesced) + histogram of dst
__global__ void __launch_bounds__(256) prep_kernel(const int* __restrict__ ei,
                                                   const int* __restrict__ an,
                                                   const float* __restrict__ el,
                                                   const float* __restrict__ ev) {
    int e = blockIdx.x * blockDim.x + threadIdx.x;
    if (e >= NE) return;

    int src = ei[e];
    int dst = ei[NE + e];
    int z   = an[src];
    float r  = el[e];
    float vx = ev[3 * e + 0];
    float vy = ev[3 * e + 1];
    float vz = ev[3 * e + 2];

    float inv = rsqrtf(vx * vx + vy * vy + vz * vz);
    float x = vx * inv, y = vy * inv, zc = vz * inv;

    float u  = r * (1.0f / 5.5f);
    float u2 = u * u;
    float u6 = u2 * u2 * u2;
    float fc = 1.0f - 28.0f * u6 + 48.0f * u6 * u - 21.0f * u6 * u2;
    fc = (u < 1.0f) ? fc : 0.0f;

    float s, c;
    sincosf(PI_F * u, &s, &c);
    float sc   = SQRT_2_CUT / r * fc;          // positive
    float twoc = 2.0f * c;

    // monomials * sc (19 muls)
    float a0 = sc;
    float a1 = x * sc,  a2 = y * sc,  a3 = zc * sc;
    float a4 = x * a1,  a5 = y * a1,  a6 = zc * a1;
    float a7 = y * a2,  a8 = zc * a2, a9 = zc * a3;
    float a10 = x * a4, a11 = y * a4, a12 = zc * a4;
    float a13 = y * a5, a14 = zc * a5, a15 = zc * a6;
    float a16 = y * a7, a17 = zc * a7, a18 = zc * a8, a19 = zc * a9;

    // sin(n*theta), n=1..8 via Chebyshev
    float s1 = s;
    float s2 = twoc * s1;
    float s3 = fmaf(twoc, s2, -s1);
    float s4 = fmaf(twoc, s3, -s2);
    float s5 = fmaf(twoc, s4, -s3);
    float s6 = fmaf(twoc, s5, -s4);
    float s7 = fmaf(twoc, s6, -s5);
    float s8 = fmaf(twoc, s7, -s6);

    float sgn = __uint_as_float(z ? 0x80000000u : 0u);

    float4* P = reinterpret_cast<float4*>(g_pay + (size_t)e * 32);
    P[0] = make_float4(a0,  a1,  a2,  a3);
    P[1] = make_float4(a4,  a5,  a6,  a7);
    P[2] = make_float4(a8,  a9,  a10, a11);
    P[3] = make_float4(a12, a13, a14, a15);
    P[4] = make_float4(a16, a17, a18, a19);
    P[5] = make_float4(sgn, 0.0f, 0.0f, 0.0f);
    P[6] = make_float4(s1, s2, s3, s4);
    P[7] = make_float4(s5, s6, s7, s8);

    atomicAdd(&g_cnt[dst], 1);
}

// Single block, 1024 threads, coalesced smem-staged scan
__global__ void __launch_bounds__(1024) scan_kernel() {
    __shared__ int sh[10240];
    __shared__ int wsum[32];
    int tid = threadIdx.x;

    for (int i = tid; i < 10240; i += 1024) sh[i] = (i < NN) ? g_cnt[i] : 0;
    __syncthreads();

    int base = tid * 10;
    int local[10];
    int sum = 0;
#pragma unroll
    for (int k = 0; k < 10; k++) { local[k] = sum; sum += sh[base + k]; }

    int lane = tid & 31, w = tid >> 5;
    int incl = sum;
#pragma unroll
    for (int d = 1; d < 32; d <<= 1) {
        int v = __shfl_up_sync(0xffffffffu, incl, d);
        if (lane >= d) incl += v;
    }
    if (lane == 31) wsum[w] = incl;
    __syncthreads();
    if (w == 0) {
        int v = wsum[lane];
        int inc2 = v;
#pragma unroll
        for (int d = 1; d < 32; d <<= 1) {
            int t2 = __shfl_up_sync(0xffffffffu, inc2, d);
            if (lane >= d) inc2 += t2;
        }
        wsum[lane] = inc2 - v;
    }
    __syncthreads();

    int excl = incl - sum + wsum[w];
#pragma unroll
    for (int k = 0; k < 10; k++) sh[base + k] = excl + local[k];
    __syncthreads();

    for (int i = tid; i < NN; i += 1024) {
        int v = sh[i];
        g_start[i]  = v;
        g_cursor[i] = v;
    }
}

__global__ void __launch_bounds__(256) order_kernel(const int* __restrict__ ei) {
    int e = blockIdx.x * blockDim.x + threadIdx.x;
    if (e >= NE) return;
    int dst = ei[NE + e];
    int pos = atomicAdd(&g_cursor[dst], 1);
    g_order[pos] = e;
}

// Warp-per-node gather: 16 FMA + 1 LOP per edge, no serial chains
__global__ void __launch_bounds__(128) gather_kernel(const int* __restrict__ an,
                                                     const float* __restrict__ W,
                                                     float* __restrict__ out) {
    __shared__ float sh[4 * 320];
    int lane   = threadIdx.x & 31;
    int warpid = threadIdx.x >> 5;
    int node   = (blockIdx.x * blockDim.x + threadIdx.x) >> 5;   // 2500 blocks * 4 warps = 10000

    int seg_s = g_start[node];
    int n_e   = g_cnt[node];
    if (lane == 0) g_cnt[node] = 0;   // restore zero state for next replay

    float accS[8], accD[8];
#pragma unroll
    for (int n = 0; n < 8; n++) { accS[n] = 0.0f; accD[n] = 0.0f; }

#pragma unroll 2
    for (int t = 0; t < n_e; t++) {
        int e = g_order[seg_s + t];                      // uniform
        const float* P = g_pay + (size_t)e * 32;
        float  mA  = P[lane];                            // lanes 0..19 meaningful
        unsigned sgn = __float_as_uint(P[20]);           // uniform, same line
        float4 qa = *reinterpret_cast<const float4*>(P + 24);
        float4 qb = *reinterpret_cast<const float4*>(P + 28);
        float  mS = __uint_as_float(__float_as_uint(mA) ^ sgn);

        accS[0] = fmaf(mA, qa.x, accS[0]);  accD[0] = fmaf(mS, qa.x, accD[0]);
        accS[1] = fmaf(mA, qa.y, accS[1]);  accD[1] = fmaf(mS, qa.y, accD[1]);
        accS[2] = fmaf(mA, qa.z, accS[2]);  accD[2] = fmaf(mS, qa.z, accD[2]);
        accS[3] = fmaf(mA, qa.w, accS[3]);  accD[3] = fmaf(mS, qa.w, accD[3]);
        accS[4] = fmaf(mA, qb.x, accS[4]);  accD[4] = fmaf(mS, qb.x, accD[4]);
        accS[5] = fmaf(mA, qb.y, accS[5]);  accD[5] = fmaf(mS, qb.y, accD[5]);
        accS[6] = fmaf(mA, qb.z, accS[6]);  accD[6] = fmaf(mS, qb.z, accD[6]);
        accS[7] = fmaf(mA, qb.w, accS[7]);  accD[7] = fmaf(mS, qb.w, accD[7]);
    }

    // Transpose through shared: [z][r][a], S0 = (S+D)/2, S1 = (S-D)/2
    float* sw = sh + warpid * 320;
    if (lane < 20) {
#pragma unroll
        for (int n = 0; n < 8; n++) {
            sw[n * 20 + lane]       = 0.5f * (accS[n] + accD[n]);
            sw[160 + n * 20 + lane] = 0.5f * (accS[n] - accD[n]);
        }
    }
    __syncwarp();

    // r-major epilogue: lane -> (r = lane/4, g = lane%4 owning a = 5g..5g+4)
    int r = lane >> 2;
    int g = lane & 3;
    const float* p0 = sw + r * 20 + g * 5;
    const float* p1 = p0 + 160;

    float W00 = W[0], W01 = W[1], W02 = W[2];
    float W10 = W[3], W11 = W[4], W12 = W[5];

    float C[5][3];
#pragma unroll
    for (int k = 0; k < 5; k++) {
        float v0 = p0[k], v1 = p1[k];
        C[k][0] = fmaf(v0, W00, v1 * W10);
        C[k][1] = fmaf(v0, W01, v1 * W11);
        C[k][2] = fmaf(v0, W02, v1 * W12);
    }

    float D0[3] = {0, 0, 0}, D1[3] = {0, 0, 0}, D2[3] = {0, 0, 0}, D3[3] = {0, 0, 0};
    if (g == 0) {
#pragma unroll
        for (int i = 0; i < 3; i++) {
            D0[i] = C[0][i];
            D1[i] = C[1][i] * C[1][i] + C[2][i] * C[2][i] + C[3][i] * C[3][i];
            D2[i] = C[4][i] * C[4][i];
        }
    } else if (g == 1) {
#pragma unroll
        for (int i = 0; i < 3; i++)
            D2[i] = 2.0f * C[0][i] * C[0][i] + 2.0f * C[1][i] * C[1][i] + C[2][i] * C[2][i]
                  + 2.0f * C[3][i] * C[3][i] + C[4][i] * C[4][i];
    } else if (g == 2) {
#pragma unroll
        for (int i = 0; i < 3; i++)
            D3[i] = C[0][i] * C[0][i] + 3.0f * C[1][i] * C[1][i] + 3.0f * C[2][i] * C[2][i]
                  + 3.0f * C[3][i] * C[3][i] + 6.0f * C[4][i] * C[4][i];
    } else {
#pragma unroll
        for (int i = 0; i < 3; i++)
            D3[i] = 3.0f * C[0][i] * C[0][i] + C[1][i] * C[1][i] + 3.0f * C[2][i] * C[2][i]
                  + 3.0f * C[3][i] * C[3][i] + C[4][i] * C[4][i];
    }

#pragma unroll
    for (int msk = 1; msk <= 2; msk <<= 1) {
#pragma unroll
        for (int i = 0; i < 3; i++) {
            D0[i] += __shfl_xor_sync(0xffffffffu, D0[i], msk);
            D1[i] += __shfl_xor_sync(0xffffffffu, D1[i], msk);
            D2[i] += __shfl_xor_sync(0xffffffffu, D2[i], msk);
            D3[i] += __shfl_xor_sync(0xffffffffu, D3[i], msk);
        }
    }

    if (g == 0) {
        int   zn = an[node];
        float e0 = zn ? W10 : W00;
        float e1 = zn ? W11 : W01;
        float e2 = zn ? W12 : W02;
        float q0 = e0 * e0, q1 = e1 * e1, q2 = e2 * e2;

        float v[36];
        v[0] = D0[0] * e0;  v[1] = D0[0] * e1;  v[2] = D0[0] * e2;
        v[3] = D0[1] * e0;  v[4] = D0[1] * e1;  v[5] = D0[1] * e2;
        v[6] = D0[2] * e0;  v[7] = D0[2] * e1;  v[8] = D0[2] * e2;

        v[9]  = D1[0] * q0; v[10] = D1[0] * q1; v[11] = D1[0] * q2;
        v[12] = D1[1] * q0; v[13] = D1[1] * q1; v[14] = D1[1] * q2;
        v[15] = D1[2] * q0; v[16] = D1[2] * q1; v[17] = D1[2] * q2;

        v[18] = D2[0] * q0; v[19] = D2[0] * q1; v[20] = D2[0] * q2;
        v[21] = D2[1] * q0; v[22] = D2[1] * q1; v[23] = D2[1] * q2;
        v[24] = D2[2] * q0; v[25] = D2[2] * q1; v[26] = D2[2] * q2;

        v[27] = D3[0] * q0; v[28] = D3[0] * q1; v[29] = D3[0] * q2;
        v[30] = D3[1] * q0; v[31] = D3[1] * q1; v[32] = D3[1] * q2;
        v[33] = D3[2] * q0; v[34] = D3[2] * q1; v[35] = D3[2] * q2;

        float4* o = reinterpret_cast<float4*>(out + (size_t)(node * 8 + r) * 36);
#pragma unroll
        for (int k = 0; k < 9; k++)
            o[k] = make_float4(v[4 * k], v[4 * k + 1], v[4 * k + 2], v[4 * k + 3]);
    }
}

extern "C" void kernel_launch(void* const* d_in, const int* in_sizes, int n_in,
                              void* d_out, int out_size) {
    const int*   an = (const int*)d_in[1];
    const int*   ei = (const int*)d_in[2];
    const float* el = (const float*)d_in[3];
    const float* ev = (const float*)d_in[4];
    const float* W  = (const float*)d_in[5];
    float* out = (float*)d_out;

    prep_kernel<<<(NE + 255) / 256, 256>>>(ei, an, el, ev);
    scan_kernel<<<1, 1024>>>();
    order_kernel<<<(NE + 255) / 256, 256>>>(ei);
    gather_kernel<<<2500, 128>>>(an, W, out);   // NN warps: 2500 blocks x 4 warps
}

// round 9
// speedup vs baseline: 1.1641x; 1.1641x over previous
#include <cuda_runtime.h>
#include <cuda_bf16.h>

#define NE 100000
#define NN 10000
#define PI_F 3.14159265358979323846f
#define SQRT_2_CUT 0.6030226891555273f

__device__ int g_cnt[NN];      // statically zero-init; gather re-zeroes after reading
__device__ int g_start[NN];
__device__ int g_cursor[NN];
// Payload per CSR slot: 32 floats (one 128B line):
// [0:20)=mon_a*sc, [20]=sign word, [21:24)=pad, [24:32)=sin(n*theta)
__device__ __align__(128) float g_pay[NE * 32];

__global__ void __launch_bounds__(256) hist_kernel(const int* __restrict__ ei) {
    int e = blockIdx.x * blockDim.x + threadIdx.x;
    if (e < NE) atomicAdd(&g_cnt[ei[NE + e]], 1);
}

// Single block, 1024 threads, coalesced smem-staged scan
__global__ void __launch_bounds__(1024) scan_kernel() {
    __shared__ int sh[10240];
    __shared__ int wsum[32];
    int tid = threadIdx.x;

    for (int i = tid; i < 10240; i += 1024) sh[i] = (i < NN) ? g_cnt[i] : 0;
    __syncthreads();

    int base = tid * 10;
    int local[10];
    int sum = 0;
#pragma unroll
    for (int k = 0; k < 10; k++) { local[k] = sum; sum += sh[base + k]; }

    int lane = tid & 31, w = tid >> 5;
    int incl = sum;
#pragma unroll
    for (int d = 1; d < 32; d <<= 1) {
        int v = __shfl_up_sync(0xffffffffu, incl, d);
        if (lane >= d) incl += v;
    }
    if (lane == 31) wsum[w] = incl;
    __syncthreads();
    if (w == 0) {
        int v = wsum[lane];
        int inc2 = v;
#pragma unroll
        for (int d = 1; d < 32; d <<= 1) {
            int t2 = __shfl_up_sync(0xffffffffu, inc2, d);
            if (lane >= d) inc2 += t2;
        }
        wsum[lane] = inc2 - v;
    }
    __syncthreads();

    int excl = incl - sum + wsum[w];
#pragma unroll
    for (int k = 0; k < 10; k++) sh[base + k] = excl + local[k];
    __syncthreads();

    for (int i = tid; i < NN; i += 1024) {
        int v = sh[i];
        g_start[i]  = v;
        g_cursor[i] = v;
    }
}

// scatter: per-edge math, payload written directly into CSR slot (one 128B line)
__global__ void __launch_bounds__(256) scatter_kernel(const int* __restrict__ ei,
                                                      const int* __restrict__ an,
                                                      const float* __restrict__ el,
                                                      const float* __restrict__ ev) {
    int e = blockIdx.x * blockDim.x + threadIdx.x;
    if (e >= NE) return;

    int src = ei[e];
    int dst = ei[NE + e];
    int z   = an[src];
    float r  = el[e];
    float vx = ev[3 * e + 0];
    float vy = ev[3 * e + 1];
    float vz = ev[3 * e + 2];

    float inv = rsqrtf(vx * vx + vy * vy + vz * vz);
    float x = vx * inv, y = vy * inv, zc = vz * inv;

    float u  = r * (1.0f / 5.5f);
    float u2 = u * u;
    float u6 = u2 * u2 * u2;
    float fc = 1.0f - 28.0f * u6 + 48.0f * u6 * u - 21.0f * u6 * u2;
    fc = (u < 1.0f) ? fc : 0.0f;

    float s, c;
    sincosf(PI_F * u, &s, &c);
    float sc   = SQRT_2_CUT / r * fc;          // positive
    float twoc = 2.0f * c;

    // monomials * sc
    float a0 = sc;
    float a1 = x * sc,  a2 = y * sc,  a3 = zc * sc;
    float a4 = x * a1,  a5 = y * a1,  a6 = zc * a1;
    float a7 = y * a2,  a8 = zc * a2, a9 = zc * a3;
    float a10 = x * a4, a11 = y * a4, a12 = zc * a4;
    float a13 = y * a5, a14 = zc * a5, a15 = zc * a6;
    float a16 = y * a7, a17 = zc * a7, a18 = zc * a8, a19 = zc * a9;

    // sin(n*theta), n=1..8 via Chebyshev
    float s1 = s;
    float s2 = twoc * s1;
    float s3 = fmaf(twoc, s2, -s1);
    float s4 = fmaf(twoc, s3, -s2);
    float s5 = fmaf(twoc, s4, -s3);
    float s6 = fmaf(twoc, s5, -s4);
    float s7 = fmaf(twoc, s6, -s5);
    float s8 = fmaf(twoc, s7, -s6);

    float sgn = __uint_as_float(z ? 0x80000000u : 0u);

    int pos = atomicAdd(&g_cursor[dst], 1);
    float4* P = reinterpret_cast<float4*>(g_pay + (size_t)pos * 32);
    P[0] = make_float4(a0,  a1,  a2,  a3);
    P[1] = make_float4(a4,  a5,  a6,  a7);
    P[2] = make_float4(a8,  a9,  a10, a11);
    P[3] = make_float4(a12, a13, a14, a15);
    P[4] = make_float4(a16, a17, a18, a19);
    P[5] = make_float4(sgn, 0.0f, 0.0f, 0.0f);
    P[6] = make_float4(s1, s2, s3, s4);
    P[7] = make_float4(s5, s6, s7, s8);
}

// Warp-per-node gather: streaming sequential payload loads, 16 FMA + 1 LOP per edge
__global__ void __launch_bounds__(128) gather_kernel(const int* __restrict__ an,
                                                     const float* __restrict__ W,
                                                     float* __restrict__ out) {
    __shared__ float sh[4 * 320];
    int lane   = threadIdx.x & 31;
    int warpid = threadIdx.x >> 5;
    int node   = (blockIdx.x * blockDim.x + threadIdx.x) >> 5;   // 2500 blocks * 4 warps = 10000

    int seg_s = g_start[node];
    int n_e   = g_cnt[node];
    if (lane == 0) g_cnt[node] = 0;   // restore zero state for next replay

    float accS[8], accD[8];
#pragma unroll
    for (int n = 0; n < 8; n++) { accS[n] = 0.0f; accD[n] = 0.0f; }

#pragma unroll 4
    for (int t = 0; t < n_e; t++) {
        const float* P = g_pay + (size_t)(seg_s + t) * 32;   // direct index: independent loads
        float  mA  = P[lane];                                // lanes 0..19 meaningful
        float4 qa  = *reinterpret_cast<const float4*>(P + 24);
        float4 qb  = *reinterpret_cast<const float4*>(P + 28);
        unsigned sgn = __float_as_uint(P[20]);
        float  mS  = __uint_as_float(__float_as_uint(mA) ^ sgn);

        accS[0] = fmaf(mA, qa.x, accS[0]);  accD[0] = fmaf(mS, qa.x, accD[0]);
        accS[1] = fmaf(mA, qa.y, accS[1]);  accD[1] = fmaf(mS, qa.y, accD[1]);
        accS[2] = fmaf(mA, qa.z, accS[2]);  accD[2] = fmaf(mS, qa.z, accD[2]);
        accS[3] = fmaf(mA, qa.w, accS[3]);  accD[3] = fmaf(mS, qa.w, accD[3]);
        accS[4] = fmaf(mA, qb.x, accS[4]);  accD[4] = fmaf(mS, qb.x, accD[4]);
        accS[5] = fmaf(mA, qb.y, accS[5]);  accD[5] = fmaf(mS, qb.y, accD[5]);
        accS[6] = fmaf(mA, qb.z, accS[6]);  accD[6] = fmaf(mS, qb.z, accD[6]);
        accS[7] = fmaf(mA, qb.w, accS[7]);  accD[7] = fmaf(mS, qb.w, accD[7]);
    }

    // Transpose through shared: [z][r][a], S0 = (S+D)/2, S1 = (S-D)/2
    float* sw = sh + warpid * 320;
    if (lane < 20) {
#pragma unroll
        for (int n = 0; n < 8; n++) {
            sw[n * 20 + lane]       = 0.5f * (accS[n] + accD[n]);
            sw[160 + n * 20 + lane] = 0.5f * (accS[n] - accD[n]);
        }
    }
    __syncwarp();

    // r-major epilogue: lane -> (r = lane/4, g = lane%4 owning a = 5g..5g+4)
    int r = lane >> 2;
    int g = lane & 3;
    const float* p0 = sw + r * 20 + g * 5;
    const float* p1 = p0 + 160;

    float W00 = W[0], W01 = W[1], W02 = W[2];
    float W10 = W[3], W11 = W[4], W12 = W[5];

    float C[5][3];
#pragma unroll
    for (int k = 0; k < 5; k++) {
        float v0 = p0[k], v1 = p1[k];
        C[k][0] = fmaf(v0, W00, v1 * W10);
        C[k][1] = fmaf(v0, W01, v1 * W11);
        C[k][2] = fmaf(v0, W02, v1 * W12);
    }

    float D0[3] = {0, 0, 0}, D1[3] = {0, 0, 0}, D2[3] = {0, 0, 0}, D3[3] = {0, 0, 0};
    if (g == 0) {
#pragma unroll
        for (int i = 0; i < 3; i++) {
            D0[i] = C[0][i];
            D1[i] = C[1][i] * C[1][i] + C[2][i] * C[2][i] + C[3][i] * C[3][i];
            D2[i] = C[4][i] * C[4][i];
        }
    } else if (g == 1) {
#pragma unroll
        for (int i = 0; i < 3; i++)
            D2[i] = 2.0f * C[0][i] * C[0][i] + 2.0f * C[1][i] * C[1][i] + C[2][i] * C[2][i]
                  + 2.0f * C[3][i] * C[3][i] + C[4][i] * C[4][i];
    } else if (g == 2) {
#pragma unroll
        for (int i = 0; i < 3; i++)
            D3[i] = C[0][i] * C[0][i] + 3.0f * C[1][i] * C[1][i] + 3.0f * C[2][i] * C[2][i]
                  + 3.0f * C[3][i] * C[3][i] + 6.0f * C[4][i] * C[4][i];
    } else {
#pragma unroll
        for (int i = 0; i < 3; i++)
            D3[i] = 3.0f * C[0][i] * C[0][i] + C[1][i] * C[1][i] + 3.0f * C[2][i] * C[2][i]
                  + 3.0f * C[3][i] * C[3][i] + C[4][i] * C[4][i];
    }

#pragma unroll
    for (int msk = 1; msk <= 2; msk <<= 1) {
#pragma unroll
        for (int i = 0; i < 3; i++) {
            D0[i] += __shfl_xor_sync(0xffffffffu, D0[i], msk);
            D1[i] += __shfl_xor_sync(0xffffffffu, D1[i], msk);
            D2[i] += __shfl_xor_sync(0xffffffffu, D2[i], msk);
            D3[i] += __shfl_xor_sync(0xffffffffu, D3[i], msk);
        }
    }

    if (g == 0) {
        int   zn = an[node];
        float e0 = zn ? W10 : W00;
        float e1 = zn ? W11 : W01;
        float e2 = zn ? W12 : W02;
        float q0 = e0 * e0, q1 = e1 * e1, q2 = e2 * e2;

        float v[36];
        v[0] = D0[0] * e0;  v[1] = D0[0] * e1;  v[2] = D0[0] * e2;
        v[3] = D0[1] * e0;  v[4] = D0[1] * e1;  v[5] = D0[1] * e2;
        v[6] = D0[2] * e0;  v[7] = D0[2] * e1;  v[8] = D0[2] * e2;

        v[9]  = D1[0] * q0; v[10] = D1[0] * q1; v[11] = D1[0] * q2;
        v[12] = D1[1] * q0; v[13] = D1[1] * q1; v[14] = D1[1] * q2;
        v[15] = D1[2] * q0; v[16] = D1[2] * q1; v[17] = D1[2] * q2;

        v[18] = D2[0] * q0; v[19] = D2[0] * q1; v[20] = D2[0] * q2;
        v[21] = D2[1] * q0; v[22] = D2[1] * q1; v[23] = D2[1] * q2;
        v[24] = D2[2] * q0; v[25] = D2[2] * q1; v[26] = D2[2] * q2;

        v[27] = D3[0] * q0; v[28] = D3[0] * q1; v[29] = D3[0] * q2;
        v[30] = D3[1] * q0; v[31] = D3[1] * q1; v[32] = D3[1] * q2;
        v[33] = D3[2] * q0; v[34] = D3[2] * q1; v[35] = D3[2] * q2;

        float4* o = reinterpret_cast<float4*>(out + (size_t)(node * 8 + r) * 36);
#pragma unroll
        for (int k = 0; k < 9; k++)
            o[k] = make_float4(v[4 * k], v[4 * k + 1], v[4 * k + 2], v[4 * k + 3]);
    }
}

extern "C" void kernel_launch(void* const* d_in, const int* in_sizes, int n_in,
                              void* d_out, int out_size) {
    const int*   an = (const int*)d_in[1];
    const int*   ei = (const int*)d_in[2];
    const float* el = (const float*)d_in[3];
    const float* ev = (const float*)d_in[4];
    const float* W  = (const float*)d_in[5];
    float* out = (float*)d_out;

    hist_kernel<<<(NE + 255) / 256, 256>>>(ei);
    scan_kernel<<<1, 1024>>>();
    scatter_kernel<<<(NE + 255) / 256, 256>>>(ei, an, el, ev);
    gather_kernel<<<2500, 128>>>(an, W, out);   // NN warps: 2500 blocks x 4 warps
}

// round 10
// speedup vs baseline: 1.1721x; 1.0068x over previous
#include <cuda_runtime.h>
#include <cuda_bf16.h>

#define NE 100000
#define NN 10000
#define PI_F 3.14159265358979323846f
#define SQRT_2_CUT 0.6030226891555273f
#define CAP 192                 // edges per smem chunk (192*128B = 24KB)

__device__ int g_cnt[NN];      // statically zero-init; gather re-zeroes after reading
__device__ int g_start[NN];
__device__ int g_cursor[NN];
// Payload per CSR slot: 32 floats (one 128B line):
// [0:20)=mon_a*sc, [20]=sign word, [21:24)=pad, [24:32)=sin(n*theta)
__device__ __align__(128) float g_pay[NE * 32];

__global__ void __launch_bounds__(256) hist_kernel(const int* __restrict__ ei) {
    int e = blockIdx.x * blockDim.x + threadIdx.x;
    if (e < NE) atomicAdd(&g_cnt[ei[NE + e]], 1);
}

// Single block, 1024 threads, coalesced smem-staged scan
__global__ void __launch_bounds__(1024) scan_kernel() {
    __shared__ int sh[10240];
    __shared__ int wsum[32];
    int tid = threadIdx.x;

    for (int i = tid; i < 10240; i += 1024) sh[i] = (i < NN) ? g_cnt[i] : 0;
    __syncthreads();

    int base = tid * 10;
    int local[10];
    int sum = 0;
#pragma unroll
    for (int k = 0; k < 10; k++) { local[k] = sum; sum += sh[base + k]; }

    int lane = tid & 31, w = tid >> 5;
    int incl = sum;
#pragma unroll
    for (int d = 1; d < 32; d <<= 1) {
        int v = __shfl_up_sync(0xffffffffu, incl, d);
        if (lane >= d) incl += v;
    }
    if (lane == 31) wsum[w] = incl;
    __syncthreads();
    if (w == 0) {
        int v = wsum[lane];
        int inc2 = v;
#pragma unroll
        for (int d = 1; d < 32; d <<= 1) {
            int t2 = __shfl_up_sync(0xffffffffu, inc2, d);
            if (lane >= d) inc2 += t2;
        }
        wsum[lane] = inc2 - v;
    }
    __syncthreads();

    int excl = incl - sum + wsum[w];
#pragma unroll
    for (int k = 0; k < 10; k++) sh[base + k] = excl + local[k];
    __syncthreads();

    for (int i = tid; i < NN; i += 1024) {
        int v = sh[i];
        g_start[i]  = v;
        g_cursor[i] = v;
    }
}

// scatter: per-edge math, payload written directly into CSR slot (one 128B line)
__global__ void __launch_bounds__(256) scatter_kernel(const int* __restrict__ ei,
                                                      const int* __restrict__ an,
                                                      const float* __restrict__ el,
                                                      const float* __restrict__ ev) {
    int e = blockIdx.x * blockDim.x + threadIdx.x;
    if (e >= NE) return;

    int src = ei[e];
    int dst = ei[NE + e];
    int z   = an[src];
    float r  = el[e];
    float vx = ev[3 * e + 0];
    float vy = ev[3 * e + 1];
    float vz = ev[3 * e + 2];

    float inv = rsqrtf(vx * vx + vy * vy + vz * vz);
    float x = vx * inv, y = vy * inv, zc = vz * inv;

    float u  = r * (1.0f / 5.5f);
    float u2 = u * u;
    float u6 = u2 * u2 * u2;
    float fc = 1.0f - 28.0f * u6 + 48.0f * u6 * u - 21.0f * u6 * u2;
    fc = (u < 1.0f) ? fc : 0.0f;

    float s, c;
    sincosf(PI_F * u, &s, &c);
    float sc   = SQRT_2_CUT / r * fc;          // positive
    float twoc = 2.0f * c;

    // monomials * sc
    float a0 = sc;
    float a1 = x * sc,  a2 = y * sc,  a3 = zc * sc;
    float a4 = x * a1,  a5 = y * a1,  a6 = zc * a1;
    float a7 = y * a2,  a8 = zc * a2, a9 = zc * a3;
    float a10 = x * a4, a11 = y * a4, a12 = zc * a4;
    float a13 = y * a5, a14 = zc * a5, a15 = zc * a6;
    float a16 = y * a7, a17 = zc * a7, a18 = zc * a8, a19 = zc * a9;

    // sin(n*theta), n=1..8 via Chebyshev
    float s1 = s;
    float s2 = twoc * s1;
    float s3 = fmaf(twoc, s2, -s1);
    float s4 = fmaf(twoc, s3, -s2);
    float s5 = fmaf(twoc, s4, -s3);
    float s6 = fmaf(twoc, s5, -s4);
    float s7 = fmaf(twoc, s6, -s5);
    float s8 = fmaf(twoc, s7, -s6);

    float sgn = __uint_as_float(z ? 0x80000000u : 0u);

    int pos = atomicAdd(&g_cursor[dst], 1);
    float4* P = reinterpret_cast<float4*>(g_pay + (size_t)pos * 32);
    P[0] = make_float4(a0,  a1,  a2,  a3);
    P[1] = make_float4(a4,  a5,  a6,  a7);
    P[2] = make_float4(a8,  a9,  a10, a11);
    P[3] = make_float4(a12, a13, a14, a15);
    P[4] = make_float4(a16, a17, a18, a19);
    P[5] = make_float4(sgn, 0.0f, 0.0f, 0.0f);
    P[6] = make_float4(s1, s2, s3, s4);
    P[7] = make_float4(s5, s6, s7, s8);
}

// Block of 256 = 8 warps handles 8 consecutive nodes (contiguous CSR range).
// Payload staged through smem in chunks; inner loop reads LDS only.
__global__ void __launch_bounds__(256) gather_kernel(const int* __restrict__ an,
                                                     const float* __restrict__ W,
                                                     float* __restrict__ out) {
    __shared__ float pay_sh[CAP * 32];    // 24KB; reused as transpose buffer post-loop
    int tid    = threadIdx.x;
    int lane   = tid & 31;
    int warpid = tid >> 5;
    int node   = blockIdx.x * 8 + warpid;        // 1250 blocks * 8 = 10000
    int node0  = blockIdx.x * 8;

    int s0  = g_start[node];
    int n_e = g_cnt[node];
    if (lane == 0) g_cnt[node] = 0;              // restore zero state for next replay
    int s1  = s0 + n_e;

    int blk_lo = g_start[node0];
    int blk_hi = g_start[node0 + 7] + g_cnt[node0 + 7];
    // note: g_cnt[node0+7] already zeroed by warp 7? Race! read before zeroing:
    // warp 7 zeroes g_cnt[node0+7] only after its own read; other warps read it here.
    // To be safe we recompute blk_hi from per-warp values via shuffle-free path below.

    float accS[8], accD[8];
#pragma unroll
    for (int n = 0; n < 8; n++) { accS[n] = 0.0f; accD[n] = 0.0f; }

    // broadcast warp7's s1 to the whole block for a race-free blk_hi
    __shared__ int sh_hi;
    if (warpid == 7 && lane == 0) sh_hi = s1;
    __syncthreads();
    blk_hi = sh_hi;

    for (int lo = blk_lo; lo < blk_hi; lo += CAP) {
        int cnt = min(CAP, blk_hi - lo);
        // cooperative load: cnt*8 float4s, coalesced
        const float4* src4 = reinterpret_cast<const float4*>(g_pay + (size_t)lo * 32);
        int n4 = cnt * 8;
        for (int i = tid; i < n4; i += 256)
            reinterpret_cast<float4*>(pay_sh)[i] = src4[i];
        __syncthreads();

        int a = max(s0, lo);
        int b = min(s1, lo + cnt);
#pragma unroll 2
        for (int t = a; t < b; t++) {
            const float* P = pay_sh + (t - lo) * 32;
            float  mA  = P[lane];                                // lanes 0..19 meaningful
            float4 qa  = *reinterpret_cast<const float4*>(P + 24);
            float4 qb  = *reinterpret_cast<const float4*>(P + 28);
            unsigned sgn = __float_as_uint(P[20]);
            float  mS  = __uint_as_float(__float_as_uint(mA) ^ sgn);

            accS[0] = fmaf(mA, qa.x, accS[0]);  accD[0] = fmaf(mS, qa.x, accD[0]);
            accS[1] = fmaf(mA, qa.y, accS[1]);  accD[1] = fmaf(mS, qa.y, accD[1]);
            accS[2] = fmaf(mA, qa.z, accS[2]);  accD[2] = fmaf(mS, qa.z, accD[2]);
            accS[3] = fmaf(mA, qa.w, accS[3]);  accD[3] = fmaf(mS, qa.w, accD[3]);
            accS[4] = fmaf(mA, qb.x, accS[4]);  accD[4] = fmaf(mS, qb.x, accD[4]);
            accS[5] = fmaf(mA, qb.y, accS[5]);  accD[5] = fmaf(mS, qb.y, accD[5]);
            accS[6] = fmaf(mA, qb.z, accS[6]);  accD[6] = fmaf(mS, qb.z, accD[6]);
            accS[7] = fmaf(mA, qb.w, accS[7]);  accD[7] = fmaf(mS, qb.w, accD[7]);
        }
        __syncthreads();   // chunk fully consumed before next overwrite / transpose reuse
    }

    // Transpose through (reused) shared: [z][r][a], S0 = (S+D)/2, S1 = (S-D)/2
    float* sw = pay_sh + warpid * 320;
    if (lane < 20) {
#pragma unroll
        for (int n = 0; n < 8; n++) {
            sw[n * 20 + lane]       = 0.5f * (accS[n] + accD[n]);
            sw[160 + n * 20 + lane] = 0.5f * (accS[n] - accD[n]);
        }
    }
    __syncwarp();

    // r-major epilogue: lane -> (r = lane/4, g = lane%4 owning a = 5g..5g+4)
    int r = lane >> 2;
    int g = lane & 3;
    const float* p0 = sw + r * 20 + g * 5;
    const float* p1 = p0 + 160;

    float W00 = W[0], W01 = W[1], W02 = W[2];
    float W10 = W[3], W11 = W[4], W12 = W[5];

    float C[5][3];
#pragma unroll
    for (int k = 0; k < 5; k++) {
        float v0 = p0[k], v1 = p1[k];
        C[k][0] = fmaf(v0, W00, v1 * W10);
        C[k][1] = fmaf(v0, W01, v1 * W11);
        C[k][2] = fmaf(v0, W02, v1 * W12);
    }

    float D0[3] = {0, 0, 0}, D1[3] = {0, 0, 0}, D2[3] = {0, 0, 0}, D3[3] = {0, 0, 0};
    if (g == 0) {
#pragma unroll
        for (int i = 0; i < 3; i++) {
            D0[i] = C[0][i];
            D1[i] = C[1][i] * C[1][i] + C[2][i] * C[2][i] + C[3][i] * C[3][i];
            D2[i] = C[4][i] * C[4][i];
        }
    } else if (g == 1) {
#pragma unroll
        for (int i = 0; i < 3; i++)
            D2[i] = 2.0f * C[0][i] * C[0][i] + 2.0f * C[1][i] * C[1][i] + C[2][i] * C[2][i]
                  + 2.0f * C[3][i] * C[3][i] + C[4][i] * C[4][i];
    } else if (g == 2) {
#pragma unroll
        for (int i = 0; i < 3; i++)
            D3[i] = C[0][i] * C[0][i] + 3.0f * C[1][i] * C[1][i] + 3.0f * C[2][i] * C[2][i]
                  + 3.0f * C[3][i] * C[3][i] + 6.0f * C[4][i] * C[4][i];
    } else {
#pragma unroll
        for (int i = 0; i < 3; i++)
            D3[i] = 3.0f * C[0][i] * C[0][i] + C[1][i] * C[1][i] + 3.0f * C[2][i] * C[2][i]
                  + 3.0f * C[3][i] * C[3][i] + C[4][i] * C[4][i];
    }

#pragma unroll
    for (int msk = 1; msk <= 2; msk <<= 1) {
#pragma unroll
        for (int i = 0; i < 3; i++) {
            D0[i] += __shfl_xor_sync(0xffffffffu, D0[i], msk);
            D1[i] += __shfl_xor_sync(0xffffffffu, D1[i], msk);
            D2[i] += __shfl_xor_sync(0xffffffffu, D2[i], msk);
            D3[i] += __shfl_xor_sync(0xffffffffu, D3[i], msk);
        }
    }

    if (g == 0) {
        int   zn = an[node];
        float e0 = zn ? W10 : W00;
        float e1 = zn ? W11 : W01;
        float e2 = zn ? W12 : W02;
        float q0 = e0 * e0, q1 = e1 * e1, q2 = e2 * e2;

        float v[36];
        v[0] = D0[0] * e0;  v[1] = D0[0] * e1;  v[2] = D0[0] * e2;
        v[3] = D0[1] * e0;  v[4] = D0[1] * e1;  v[5] = D0[1] * e2;
        v[6] = D0[2] * e0;  v[7] = D0[2] * e1;  v[8] = D0[2] * e2;

        v[9]  = D1[0] * q0; v[10] = D1[0] * q1; v[11] = D1[0] * q2;
        v[12] = D1[1] * q0; v[13] = D1[1] * q1; v[14] = D1[1] * q2;
        v[15] = D1[2] * q0; v[16] = D1[2] * q1; v[17] = D1[2] * q2;

        v[18] = D2[0] * q0; v[19] = D2[0] * q1; v[20] = D2[0] * q2;
        v[21] = D2[1] * q0; v[22] = D2[1] * q1; v[23] = D2[1] * q2;
        v[24] = D2[2] * q0; v[25] = D2[2] * q1; v[26] = D2[2] * q2;

        v[27] = D3[0] * q0; v[28] = D3[0] * q1; v[29] = D3[0] * q2;
        v[30] = D3[1] * q0; v[31] = D3[1] * q1; v[32] = D3[1] * q2;
        v[33] = D3[2] * q0; v[34] = D3[2] * q1; v[35] = D3[2] * q2;

        float4* o = reinterpret_cast<float4*>(out + (size_t)(node * 8 + r) * 36);
#pragma unroll
        for (int k = 0; k < 9; k++)
            o[k] = make_float4(v[4 * k], v[4 * k + 1], v[4 * k + 2], v[4 * k + 3]);
    }
}

extern "C" void kernel_launch(void* const* d_in, const int* in_sizes, int n_in,
                              void* d_out, int out_size) {
    const int*   an = (const int*)d_in[1];
    const int*   ei = (const int*)d_in[2];
    const float* el = (const float*)d_in[3];
    const float* ev = (const float*)d_in[4];
    const float* W  = (const float*)d_in[5];
    float* out = (float*)d_out;

    hist_kernel<<<(NE + 255) / 256, 256>>>(ei);
    scan_kernel<<<1, 1024>>>();
    scatter_kernel<<<(NE + 255) / 256, 256>>>(ei, an, el, ev);
    gather_kernel<<<1250, 256>>>(an, W, out);   // 8 nodes per block
}